// round 4
// baseline (speedup 1.0000x reference)
#include <cuda_runtime.h>
#include <math.h>

// Problem dims
constexpr int NB = 64;     // batch
constexpr int NT = 256;    // time
constexpr int ND = 1024;   // input dim
constexpr int NH = 1024;   // hidden
constexpr int NG = 4096;   // 4*NH (gates i,f,g,o)

// ---------------------------------------------------------------------------
// Scratch state (device globals: allocation-free per harness rules)
// ---------------------------------------------------------------------------
__device__ float g_xpre[(size_t)NT * NB * NG];  // x @ Wx0 + b0, [t][b][4H]  (256 MB)
__device__ float g_h0[2][NB * NH];              // ping-pong by t parity
__device__ float g_h1[2][NB * NH];
__device__ float g_c0[NB * NH];
__device__ float g_c1[NB * NH];

// ---------------------------------------------------------------------------
// Packed f32x2 helpers (Blackwell packed fp32: 2x FFMA throughput vs 3-reg FFMA)
// ---------------------------------------------------------------------------
__device__ __forceinline__ unsigned long long pack2(float lo, float hi) {
    unsigned long long r;
    asm("mov.b64 %0, {%1, %2};" : "=l"(r) : "f"(lo), "f"(hi));
    return r;
}
__device__ __forceinline__ unsigned long long dup2(float v) {
    unsigned long long r;
    asm("mov.b64 %0, {%1, %1};" : "=l"(r) : "f"(v));
    return r;
}
__device__ __forceinline__ void fma2(unsigned long long& acc,
                                     unsigned long long a, unsigned long long b) {
    asm("fma.rn.f32x2 %0, %1, %2, %0;" : "+l"(acc) : "l"(a), "l"(b));
}
__device__ __forceinline__ void unpack2(unsigned long long v, float& lo, float& hi) {
    asm("mov.b64 {%0, %1}, %2;" : "=f"(lo), "=f"(hi) : "l"(v));
}
__device__ __forceinline__ float sigmoidf_(float x) { return 1.0f / (1.0f + expf(-x)); }

// ---------------------------------------------------------------------------
// Zero recurrent state (must run every launch: graph replays reuse globals)
// ---------------------------------------------------------------------------
__global__ void init_state_kernel() {
    int i = blockIdx.x * blockDim.x + threadIdx.x;
    if (i < NB * NH) {
        g_h0[0][i] = 0.f; g_h0[1][i] = 0.f;
        g_h1[0][i] = 0.f; g_h1[1][i] = 0.f;
        g_c0[i] = 0.f;    g_c1[i] = 0.f;
    }
}

// ---------------------------------------------------------------------------
// Precompute: Xpre[t*NB+b][n] = sum_k x[b][t][k] * Wx0[k][n] + b0[n]
// GEMM M=16384 (rows (t,b)), N=4096, K=1024. Tile 128x64, BK=16, 256 thr, 8x4/thr.
// ---------------------------------------------------------------------------
__global__ __launch_bounds__(256) void precompute_kernel(
    const float* __restrict__ x, const float* __restrict__ Wx0,
    const float* __restrict__ b0)
{
    constexpr int BK = 16;
    __shared__ float As[BK][132];   // [k][m], row stride 132 floats (16B aligned)
    __shared__ float Ws[BK][64];    // [k][n]

    const int tid = threadIdx.x;          // 256
    const int tc = tid & 15;              // 16 col-threads * 4  = 64 cols
    const int tr = tid >> 4;              // 16 row-threads * 8  = 128 rows
    const int col0 = blockIdx.x * 64;
    const int row0 = blockIdx.y * 128;

    unsigned long long acc[8][2];
#pragma unroll
    for (int i = 0; i < 8; i++) { acc[i][0] = 0ull; acc[i][1] = 0ull; }

    for (int k0 = 0; k0 < ND; k0 += BK) {
        // Load A tile: 128 rows x 16 k = 512 float4, lanes r-fast (conflict-free STS)
#pragma unroll
        for (int i = 0; i < 2; i++) {
            int idx = tid + i * 256;          // 0..511
            int r   = idx & 127;
            int kq  = (idx >> 7) << 2;        // 0,4,8,12
            int grow = row0 + r;
            int tt = grow >> 6;               // t = row / 64
            int bb = grow & 63;               // b = row % 64
            float4 v = *(const float4*)&x[((size_t)bb * NT + tt) * ND + k0 + kq];
            As[kq + 0][r] = v.x; As[kq + 1][r] = v.y;
            As[kq + 2][r] = v.z; As[kq + 3][r] = v.w;
        }
        // Load W tile: 16 k x 64 n = 256 float4, 1 per thread, coalesced
        {
            int kk = tid >> 4;
            int nq = (tid & 15) << 2;
            *(float4*)&Ws[kk][nq] =
                *(const float4*)&Wx0[(size_t)(k0 + kk) * NG + col0 + nq];
        }
        __syncthreads();

#pragma unroll
        for (int kk = 0; kk < BK; kk++) {
            float4 a0 = *(const float4*)&As[kk][tr * 8];
            float4 a1 = *(const float4*)&As[kk][tr * 8 + 4];
            float4 wv = *(const float4*)&Ws[kk][tc * 4];
            unsigned long long w01 = pack2(wv.x, wv.y);
            unsigned long long w23 = pack2(wv.z, wv.w);
            float ar[8] = {a0.x, a0.y, a0.z, a0.w, a1.x, a1.y, a1.z, a1.w};
#pragma unroll
            for (int i = 0; i < 8; i++) {
                unsigned long long ad = dup2(ar[i]);
                fma2(acc[i][0], ad, w01);
                fma2(acc[i][1], ad, w23);
            }
        }
        __syncthreads();
    }

    // Epilogue: add bias, store
    const int c = col0 + tc * 4;
    float4 bb4 = *(const float4*)&b0[c];
#pragma unroll
    for (int i = 0; i < 8; i++) {
        int grow = row0 + tr * 8 + i;
        float v0, v1, v2, v3;
        unpack2(acc[i][0], v0, v1);
        unpack2(acc[i][1], v2, v3);
        float4 o;
        o.x = v0 + bb4.x; o.y = v1 + bb4.y; o.z = v2 + bb4.z; o.w = v3 + bb4.w;
        *(float4*)&g_xpre[(size_t)grow * NG + c] = o;
    }
}

// ---------------------------------------------------------------------------
// One LSTM cell step (one layer). Fused GEMM + gate activations + cell update.
//   layer 0: gates = Xpre[t] + h0_prev @ Wh0                      (K=1024)
//   layer 1: gates = b1 + h0_new @ Wx1 + h1_prev @ Wh1            (K=2048)
// Block = 32 batch-rows x 16 j-cols (=> 64 gate cols: i/f/g/o slices of same j),
// grid (64, 2) = 128 blocks, 128 threads, 4x4 reg tile, BK=32,
// register-staged global->smem pipeline (1 block/SM must self-hide L2 latency).
// ---------------------------------------------------------------------------
__global__ __launch_bounds__(128) void lstm_step_kernel(
    int layer, int t,
    const float* __restrict__ W1p,   // Wh0 (L0) or Wx1 (L1)
    const float* __restrict__ W2p,   // Wh1 (L1) or null
    const float* __restrict__ biasp) // b1 (L1) or null
{
    constexpr int BK = 32;
    __shared__ float As[BK][36];     // [k][m], stride 36 floats (16B aligned)
    __shared__ float Ws[BK][64];     // [k][gatecol]
    __shared__ float gsm[32][65];    // gate staging for cell update

    const int tid = threadIdx.x;     // 128
    const int tc  = tid & 15;        // 16 col-threads * 4 = 64 gate cols
    const int tr  = tid >> 4;        // 8 row-threads * 4 = 32 rows
    const int j0   = blockIdx.x * 16;
    const int row0 = blockIdx.y * 32;

    const int cur = t & 1, nxt = cur ^ 1;
    const float* A1;
    const float* A2 = nullptr;
    const float* base_rc = nullptr;  // per-(b,col) additive (Xpre slice)
    const float* base_c  = nullptr;  // per-col additive (bias)
    float* cS; float* hOut;
    if (layer == 0) {
        A1 = g_h0[cur];
        base_rc = g_xpre + (size_t)t * NB * NG;
        cS = g_c0; hOut = g_h0[nxt];
    } else {
        A1 = g_h0[nxt];              // h0 of CURRENT timestep (written by layer0)
        A2 = g_h1[cur];
        base_c = biasp;
        cS = g_c1; hOut = g_h1[nxt];
    }

    const int nseg = (layer == 0) ? 1 : 2;
    const float* Aseg[2] = {A1, A2};
    const float* Wseg[2] = {W1p, W2p};

    unsigned long long acc[4][2];
#pragma unroll
    for (int i = 0; i < 4; i++) { acc[i][0] = 0ull; acc[i][1] = 0ull; }

    float4 aReg[2], wReg[4];

    // Prologue: load chunk 0 into registers
    {
        const float* A = Aseg[0]; const float* W = Wseg[0];
#pragma unroll
        for (int i = 0; i < 2; i++) {
            int idx = tid + i * 128;                 // 0..255
            int r = idx & 31; int kq = (idx >> 5) << 2;
            aReg[i] = *(const float4*)(A + (size_t)(row0 + r) * NH + kq);
        }
#pragma unroll
        for (int i = 0; i < 4; i++) {
            int idx = tid + i * 128;                 // 0..511
            int kk = idx >> 4; int rem = idx & 15;
            int g = rem >> 2; int jq = (rem & 3) << 2;
            wReg[i] = *(const float4*)(W + (size_t)kk * NG + g * NH + j0 + jq);
        }
    }

    const int nchunks = nseg * (NH / BK);
    for (int ch = 0; ch < nchunks; ch++) {
        __syncthreads();   // previous compute done before smem overwrite
        // Stage registers -> smem
#pragma unroll
        for (int i = 0; i < 2; i++) {
            int idx = tid + i * 128;
            int r = idx & 31; int kq = (idx >> 5) << 2;
            As[kq + 0][r] = aReg[i].x; As[kq + 1][r] = aReg[i].y;
            As[kq + 2][r] = aReg[i].z; As[kq + 3][r] = aReg[i].w;
        }
#pragma unroll
        for (int i = 0; i < 4; i++) {
            int idx = tid + i * 128;
            int kk = idx >> 4; int rem = idx & 15;
            *(float4*)&Ws[kk][((rem >> 2) << 4) + ((rem & 3) << 2)] = wReg[i];
        }
        __syncthreads();

        // Prefetch next chunk (overlaps with compute below)
        if (ch + 1 < nchunks) {
            int nc = ch + 1;
            int s  = nc / (NH / BK);
            int k0 = (nc % (NH / BK)) * BK;
            const float* A = Aseg[s]; const float* W = Wseg[s];
#pragma unroll
            for (int i = 0; i < 2; i++) {
                int idx = tid + i * 128;
                int r = idx & 31; int kq = (idx >> 5) << 2;
                aReg[i] = *(const float4*)(A + (size_t)(row0 + r) * NH + k0 + kq);
            }
#pragma unroll
            for (int i = 0; i < 4; i++) {
                int idx = tid + i * 128;
                int kk = idx >> 4; int rem = idx & 15;
                int g = rem >> 2; int jq = (rem & 3) << 2;
                wReg[i] = *(const float4*)(W + (size_t)(k0 + kk) * NG + g * NH + j0 + jq);
            }
        }

        // Compute BK k-steps with packed f32x2 FMAs
#pragma unroll
        for (int kk = 0; kk < BK; kk++) {
            float4 av = *(const float4*)&As[kk][tr << 2];
            float4 wv = *(const float4*)&Ws[kk][tc << 2];
            unsigned long long w01 = pack2(wv.x, wv.y);
            unsigned long long w23 = pack2(wv.z, wv.w);
            float ar[4] = {av.x, av.y, av.z, av.w};
#pragma unroll
            for (int i = 0; i < 4; i++) {
                unsigned long long ad = dup2(ar[i]);
                fma2(acc[i][0], ad, w01);
                fma2(acc[i][1], ad, w23);
            }
        }
    }
    __syncthreads();

    // Stage gate pre-activations to smem (threads own scattered gate cols)
#pragma unroll
    for (int i = 0; i < 4; i++) {
        float v0, v1, v2, v3;
        unpack2(acc[i][0], v0, v1);
        unpack2(acc[i][1], v2, v3);
        int r = (tr << 2) + i, c = (tc << 2);
        gsm[r][c] = v0; gsm[r][c + 1] = v1; gsm[r][c + 2] = v2; gsm[r][c + 3] = v3;
    }
    __syncthreads();

    // Cell update: 32 rows x 16 j-cols = 512 elems, 4 per thread
#pragma unroll
    for (int u = 0; u < 4; u++) {
        int idx = tid + (u << 7);
        int r = idx >> 4, jj = idx & 15;
        float ig = gsm[r][jj];
        float fg = gsm[r][16 + jj];
        float gg = gsm[r][32 + jj];
        float og = gsm[r][48 + jj];
        int b = row0 + r;
        int col = j0 + jj;
        if (base_rc) {
            const float* p = base_rc + (size_t)b * NG + col;
            ig += p[0]; fg += p[NH]; gg += p[2 * NH]; og += p[3 * NH];
        } else {
            const float* p = base_c + col;
            ig += p[0]; fg += p[NH]; gg += p[2 * NH]; og += p[3 * NH];
        }
        int ci = b * NH + col;
        float cv = cS[ci];
        float is = sigmoidf_(ig), fs = sigmoidf_(fg);
        float gt = tanhf(gg),     os = sigmoidf_(og);
        float cn = fs * cv + is * gt;
        cS[ci] = cn;
        hOut[ci] = os * tanhf(cn);
    }
}

// ---------------------------------------------------------------------------
// Copy final top-layer hidden state to output. After t = NT-1 (odd), layer1
// wrote g_h1[nxt = 0].
// ---------------------------------------------------------------------------
__global__ void copy_out_kernel(float* __restrict__ out) {
    int i = blockIdx.x * blockDim.x + threadIdx.x;
    if (i < NB * NH) out[i] = g_h1[0][i];
}

// ---------------------------------------------------------------------------
// kernel_launch: graph-capturable, allocation-free, deterministic.
// Inputs (metadata order): x, Wx0, Wh0, b0, Wx1, Wh1, b1. Output: h1 [64,1024].
// ---------------------------------------------------------------------------
extern "C" void kernel_launch(void* const* d_in, const int* in_sizes, int n_in,
                              void* d_out, int out_size) {
    const float* x   = (const float*)d_in[0];
    const float* Wx0 = (const float*)d_in[1];
    const float* Wh0 = (const float*)d_in[2];
    const float* b0  = (const float*)d_in[3];
    const float* Wx1 = (const float*)d_in[4];
    const float* Wh1 = (const float*)d_in[5];
    const float* b1  = (const float*)d_in[6];
    float* out = (float*)d_out;

    (void)in_sizes; (void)n_in; (void)out_size;

    // Re-zero state every call (graph replays reuse device globals)
    init_state_kernel<<<(NB * NH + 255) / 256, 256>>>();

    // Phase 1: all-timestep input projection for layer 0
    precompute_kernel<<<dim3(NG / 64, (NT * NB) / 128), 256>>>(x, Wx0, b0);

    // Phase 2: sequential recurrence, 2 launches per timestep
    for (int t = 0; t < NT; t++) {
        lstm_step_kernel<<<dim3(NH / 16, 2), 128>>>(0, t, Wh0, nullptr, nullptr);
        lstm_step_kernel<<<dim3(NH / 16, 2), 128>>>(1, t, Wx1, Wh1, b1);
    }

    copy_out_kernel<<<(NB * NH + 1023) / 1024, 1024>>>(out);
}